// round 1
// baseline (speedup 1.0000x reference)
#include <cuda_runtime.h>

// Problem dims (fixed by reference)
#define BB 8
#define CC 64
#define HH 64
#define WW 512
#define WT 64          // w-tile
#define SP 68          // padded smem row stride (floats): 4*SP % 128B pattern breaks conflicts

// Smem layout (floats):
//  sWq [64*64]  transposed weights: sW[i*64 + o] = W[o][i]
//  sWk [64*64]
//  sWv [64*64]
//  sB  [3*64]   biases (q,k,v)
//  sX  [64*SP]  input tile  [i][wl]   (k tile in phase1, q tile in phase2)
//  sV  [64*SP]  v tile      [i][wl]
//  sXP [64*SP]  projected   [wl][o]   (kp in phase1, qp in phase2)
//  sVP [64*SP]  projected   [wl][o]   (vp)
//  sM  [64*SP]  M[c1][c2]
#define SM_FLOATS (3*64*64 + 3*64 + 5*64*SP)
#define SM_BYTES  (SM_FLOATS * 4)

__device__ __forceinline__ void proj16(const float* __restrict__ xs,
                                       const float* __restrict__ wts,
                                       const float* __restrict__ bias,
                                       float* __restrict__ outp,
                                       int wl, int og)
{
    float acc[16];
#pragma unroll
    for (int j = 0; j < 16; j++) acc[j] = bias[og + j];

#pragma unroll 8
    for (int i = 0; i < 64; i++) {
        float xv = xs[i * SP + wl];
        const float4* wr = reinterpret_cast<const float4*>(wts + i * 64 + og);
#pragma unroll
        for (int j4 = 0; j4 < 4; j4++) {
            float4 wv = wr[j4];
            acc[4*j4+0] += wv.x * xv;
            acc[4*j4+1] += wv.y * xv;
            acc[4*j4+2] += wv.z * xv;
            acc[4*j4+3] += wv.w * xv;
        }
    }
#pragma unroll
    for (int j4 = 0; j4 < 4; j4++) {
        *reinterpret_cast<float4*>(outp + wl * SP + og + 4*j4) =
            make_float4(acc[4*j4+0], acc[4*j4+1], acc[4*j4+2], acc[4*j4+3]);
    }
}

__device__ __forceinline__ void loadTile(float* __restrict__ dst,
                                         const float* __restrict__ src,
                                         int w0, int tid)
{
#pragma unroll
    for (int j = 0; j < 16; j++) {
        int n  = tid + 256 * j;
        int i  = n >> 6;
        int wl = n & 63;
        dst[i * SP + wl] = __ldg(src + (size_t)i * (HH * WW) + w0 + wl);
    }
}

__global__ __launch_bounds__(256, 1)
void mha_fused(const float* __restrict__ q, const float* __restrict__ k,
               const float* __restrict__ v,
               const float* __restrict__ Wq, const float* __restrict__ bq,
               const float* __restrict__ Wk, const float* __restrict__ bk,
               const float* __restrict__ Wv, const float* __restrict__ bv,
               float* __restrict__ out)
{
    extern __shared__ float sm[];
    float* sWq = sm;
    float* sWk = sm + 4096;
    float* sWv = sm + 8192;
    float* sB  = sm + 12288;            // [3*64]
    float* sX  = sm + 12288 + 192;      // [64*SP]
    float* sV  = sX  + 64 * SP;
    float* sXP = sV  + 64 * SP;
    float* sVP = sXP + 64 * SP;
    float* sM  = sVP + 64 * SP;

    const int tid = threadIdx.x;
    const int h = blockIdx.x;
    const int b = blockIdx.y;

    const size_t base = (size_t)b * CC * HH * WW + (size_t)h * WW;
    const float* qb = q + base;
    const float* kb = k + base;
    const float* vb = v + base;
    float*       ob = out + base;

    // ---- stage transposed weights + biases ----
    for (int n = tid; n < 4096; n += 256) {
        int o = n & 63, i = n >> 6;                 // coalesced STS, gmem col-read (L2-cached)
        sWq[i * 64 + o] = Wq[o * 64 + i];
        sWk[i * 64 + o] = Wk[o * 64 + i];
        sWv[i * 64 + o] = Wv[o * 64 + i];
    }
    if (tid < 64) {
        sB[tid]       = bq[tid];
        sB[64  + tid] = bk[tid];
        sB[128 + tid] = bv[tid];
    }
    __syncthreads();

    // thread mappings
    const int wl  = tid & 63;            // proj: one w column
    const int og  = (tid >> 6) * 16;     // proj: 16 output channels
    const int c1  = 4 * (tid >> 4);      // M: 4 rows
    const int c2  = 4 * (tid & 15);      // M / out: 4 cols
    const int wb  = 4 * (tid >> 4);      // phase2 out: 4 w rows

    // ---- Phase 1: M[c1][c2] = sum_w kp[w][c1] * vp[w][c2] ----
    float mAcc[16];
#pragma unroll
    for (int j = 0; j < 16; j++) mAcc[j] = 0.0f;

    for (int t = 0; t < WW / WT; t++) {
        const int w0 = t * WT;
        loadTile(sX, kb, w0, tid);
        loadTile(sV, vb, w0, tid);
        __syncthreads();

        proj16(sX, sWk, sB + 64,  sXP, wl, og);   // kp
        proj16(sV, sWv, sB + 128, sVP, wl, og);   // vp
        __syncthreads();

#pragma unroll 4
        for (int w = 0; w < WT; w++) {
            float4 a  = *reinterpret_cast<const float4*>(sXP + w * SP + c1);
            float4 bv4 = *reinterpret_cast<const float4*>(sVP + w * SP + c2);
            mAcc[ 0] += a.x * bv4.x;  mAcc[ 1] += a.x * bv4.y;
            mAcc[ 2] += a.x * bv4.z;  mAcc[ 3] += a.x * bv4.w;
            mAcc[ 4] += a.y * bv4.x;  mAcc[ 5] += a.y * bv4.y;
            mAcc[ 6] += a.y * bv4.z;  mAcc[ 7] += a.y * bv4.w;
            mAcc[ 8] += a.z * bv4.x;  mAcc[ 9] += a.z * bv4.y;
            mAcc[10] += a.z * bv4.z;  mAcc[11] += a.z * bv4.w;
            mAcc[12] += a.w * bv4.x;  mAcc[13] += a.w * bv4.y;
            mAcc[14] += a.w * bv4.z;  mAcc[15] += a.w * bv4.w;
        }
        __syncthreads();
    }

    // write M to smem
#pragma unroll
    for (int j = 0; j < 4; j++) {
        *reinterpret_cast<float4*>(sM + (c1 + j) * SP + c2) =
            make_float4(mAcc[j*4+0], mAcc[j*4+1], mAcc[j*4+2], mAcc[j*4+3]);
    }
    __syncthreads();

    // ---- Phase 2: out[w][c2] = sum_c1 qp[w][c1] * M[c1][c2]  (+ residual q) ----
    for (int t = 0; t < WW / WT; t++) {
        const int w0 = t * WT;
        loadTile(sX, qb, w0, tid);                 // q tile (also residual)
        __syncthreads();

        proj16(sX, sWq, sB, sXP, wl, og);          // qp
        __syncthreads();

        float acc[16];                              // acc[r*4+kk] = out[wb+r][c2+kk]
#pragma unroll
        for (int j = 0; j < 16; j++) acc[j] = 0.0f;

#pragma unroll 2
        for (int c1i = 0; c1i < 64; c1i += 4) {
            float4 mv0 = *reinterpret_cast<const float4*>(sM + (c1i + 0) * SP + c2);
            float4 mv1 = *reinterpret_cast<const float4*>(sM + (c1i + 1) * SP + c2);
            float4 mv2 = *reinterpret_cast<const float4*>(sM + (c1i + 2) * SP + c2);
            float4 mv3 = *reinterpret_cast<const float4*>(sM + (c1i + 3) * SP + c2);
#pragma unroll
            for (int r = 0; r < 4; r++) {
                float4 qv = *reinterpret_cast<const float4*>(sXP + (wb + r) * SP + c1i);
                acc[r*4+0] += qv.x*mv0.x + qv.y*mv1.x + qv.z*mv2.x + qv.w*mv3.x;
                acc[r*4+1] += qv.x*mv0.y + qv.y*mv1.y + qv.z*mv2.y + qv.w*mv3.y;
                acc[r*4+2] += qv.x*mv0.z + qv.y*mv1.z + qv.z*mv2.z + qv.w*mv3.z;
                acc[r*4+3] += qv.x*mv0.w + qv.y*mv1.w + qv.z*mv2.w + qv.w*mv3.w;
            }
        }

        // residual add + coalesced store (output layout [b][c][h][w])
#pragma unroll
        for (int kk = 0; kk < 4; kk++) {
            int cch = c2 + kk;
            float4 r4 = *reinterpret_cast<const float4*>(sX + cch * SP + wb);
            float4 o4 = make_float4(acc[0*4+kk] + r4.x, acc[1*4+kk] + r4.y,
                                    acc[2*4+kk] + r4.z, acc[3*4+kk] + r4.w);
            *reinterpret_cast<float4*>(ob + (size_t)cch * (HH * WW) + w0 + wb) = o4;
        }
        __syncthreads();
    }
}

extern "C" void kernel_launch(void* const* d_in, const int* in_sizes, int n_in,
                              void* d_out, int out_size)
{
    const float* q  = (const float*)d_in[0];
    const float* k  = (const float*)d_in[1];
    const float* v  = (const float*)d_in[2];
    const float* Wq = (const float*)d_in[3];
    const float* bq = (const float*)d_in[4];
    const float* Wk = (const float*)d_in[5];
    const float* bk = (const float*)d_in[6];
    const float* Wv = (const float*)d_in[7];
    const float* bv = (const float*)d_in[8];
    float* out = (float*)d_out;

    cudaFuncSetAttribute(mha_fused, cudaFuncAttributeMaxDynamicSharedMemorySize, SM_BYTES);

    dim3 grid(HH, BB);
    mha_fused<<<grid, 256, SM_BYTES>>>(q, k, v, Wq, bq, Wk, bk, Wv, bv, out);
}

// round 3
// speedup vs baseline: 1.0005x; 1.0005x over previous
#include <cuda_runtime.h>

// Problem dims (fixed by reference)
#define BB 8
#define CC 64
#define HH 64
#define WW 512
#define WT 64          // w-tile
#define SP 68          // padded smem row stride (floats): 4*SP % 128B pattern breaks conflicts

// Smem layout (floats):
//  sWq [64*64]  transposed weights: sW[i*64 + o] = W[o][i]
//  sWk [64*64]
//  sWv [64*64]
//  sB  [3*64]   biases (q,k,v)
//  sX  [64*SP]  input tile  [i][wl]   (k tile in phase1, q tile in phase2)
//  sV  [64*SP]  v tile      [i][wl]
//  sXP [64*SP]  projected   [wl][o]   (kp in phase1, qp in phase2)
//  sVP [64*SP]  projected   [wl][o]   (vp)
//  sM  [64*SP]  M[c1][c2]
#define SM_FLOATS (3*64*64 + 3*64 + 5*64*SP)
#define SM_BYTES  (SM_FLOATS * 4)

__device__ __forceinline__ void proj16(const float* __restrict__ xs,
                                       const float* __restrict__ wts,
                                       const float* __restrict__ bias,
                                       float* __restrict__ outp,
                                       int wl, int og)
{
    float acc[16];
#pragma unroll
    for (int j = 0; j < 16; j++) acc[j] = bias[og + j];

#pragma unroll 8
    for (int i = 0; i < 64; i++) {
        float xv = xs[i * SP + wl];
        const float4* wr = reinterpret_cast<const float4*>(wts + i * 64 + og);
#pragma unroll
        for (int j4 = 0; j4 < 4; j4++) {
            float4 wv = wr[j4];
            acc[4*j4+0] += wv.x * xv;
            acc[4*j4+1] += wv.y * xv;
            acc[4*j4+2] += wv.z * xv;
            acc[4*j4+3] += wv.w * xv;
        }
    }
#pragma unroll
    for (int j4 = 0; j4 < 4; j4++) {
        *reinterpret_cast<float4*>(outp + wl * SP + og + 4*j4) =
            make_float4(acc[4*j4+0], acc[4*j4+1], acc[4*j4+2], acc[4*j4+3]);
    }
}

__device__ __forceinline__ void loadTile(float* __restrict__ dst,
                                         const float* __restrict__ src,
                                         int w0, int tid)
{
#pragma unroll
    for (int j = 0; j < 16; j++) {
        int n  = tid + 256 * j;
        int i  = n >> 6;
        int wl = n & 63;
        dst[i * SP + wl] = __ldg(src + (size_t)i * (HH * WW) + w0 + wl);
    }
}

__global__ __launch_bounds__(256, 1)
void mha_fused(const float* __restrict__ q, const float* __restrict__ k,
               const float* __restrict__ v,
               const float* __restrict__ Wq, const float* __restrict__ bq,
               const float* __restrict__ Wk, const float* __restrict__ bk,
               const float* __restrict__ Wv, const float* __restrict__ bv,
               float* __restrict__ out)
{
    extern __shared__ float sm[];
    float* sWq = sm;
    float* sWk = sm + 4096;
    float* sWv = sm + 8192;
    float* sB  = sm + 12288;            // [3*64]
    float* sX  = sm + 12288 + 192;      // [64*SP]
    float* sV  = sX  + 64 * SP;
    float* sXP = sV  + 64 * SP;
    float* sVP = sXP + 64 * SP;
    float* sM  = sVP + 64 * SP;

    const int tid = threadIdx.x;
    const int h = blockIdx.x;
    const int b = blockIdx.y;

    const size_t base = (size_t)b * CC * HH * WW + (size_t)h * WW;
    const float* qb = q + base;
    const float* kb = k + base;
    const float* vb = v + base;
    float*       ob = out + base;

    // ---- stage transposed weights + biases ----
    for (int n = tid; n < 4096; n += 256) {
        int o = n & 63, i = n >> 6;                 // coalesced STS, gmem col-read (L2-cached)
        sWq[i * 64 + o] = Wq[o * 64 + i];
        sWk[i * 64 + o] = Wk[o * 64 + i];
        sWv[i * 64 + o] = Wv[o * 64 + i];
    }
    if (tid < 64) {
        sB[tid]       = bq[tid];
        sB[64  + tid] = bk[tid];
        sB[128 + tid] = bv[tid];
    }
    __syncthreads();

    // thread mappings
    const int wl  = tid & 63;            // proj: one w column
    const int og  = (tid >> 6) * 16;     // proj: 16 output channels
    const int c1  = 4 * (tid >> 4);      // M: 4 rows
    const int c2  = 4 * (tid & 15);      // M / out: 4 cols
    const int wb  = 4 * (tid >> 4);      // phase2 out: 4 w rows

    // ---- Phase 1: M[c1][c2] = sum_w kp[w][c1] * vp[w][c2] ----
    float mAcc[16];
#pragma unroll
    for (int j = 0; j < 16; j++) mAcc[j] = 0.0f;

    for (int t = 0; t < WW / WT; t++) {
        const int w0 = t * WT;
        loadTile(sX, kb, w0, tid);
        loadTile(sV, vb, w0, tid);
        __syncthreads();

        proj16(sX, sWk, sB + 64,  sXP, wl, og);   // kp
        proj16(sV, sWv, sB + 128, sVP, wl, og);   // vp
        __syncthreads();

#pragma unroll 4
        for (int w = 0; w < WT; w++) {
            float4 a  = *reinterpret_cast<const float4*>(sXP + w * SP + c1);
            float4 bv4 = *reinterpret_cast<const float4*>(sVP + w * SP + c2);
            mAcc[ 0] += a.x * bv4.x;  mAcc[ 1] += a.x * bv4.y;
            mAcc[ 2] += a.x * bv4.z;  mAcc[ 3] += a.x * bv4.w;
            mAcc[ 4] += a.y * bv4.x;  mAcc[ 5] += a.y * bv4.y;
            mAcc[ 6] += a.y * bv4.z;  mAcc[ 7] += a.y * bv4.w;
            mAcc[ 8] += a.z * bv4.x;  mAcc[ 9] += a.z * bv4.y;
            mAcc[10] += a.z * bv4.z;  mAcc[11] += a.z * bv4.w;
            mAcc[12] += a.w * bv4.x;  mAcc[13] += a.w * bv4.y;
            mAcc[14] += a.w * bv4.z;  mAcc[15] += a.w * bv4.w;
        }
        __syncthreads();
    }

    // write M to smem
#pragma unroll
    for (int j = 0; j < 4; j++) {
        *reinterpret_cast<float4*>(sM + (c1 + j) * SP + c2) =
            make_float4(mAcc[j*4+0], mAcc[j*4+1], mAcc[j*4+2], mAcc[j*4+3]);
    }
    __syncthreads();

    // ---- Phase 2: out[w][c2] = sum_c1 qp[w][c1] * M[c1][c2]  (+ residual q) ----
    for (int t = 0; t < WW / WT; t++) {
        const int w0 = t * WT;
        loadTile(sX, qb, w0, tid);                 // q tile (also residual)
        __syncthreads();

        proj16(sX, sWq, sB, sXP, wl, og);          // qp
        __syncthreads();

        float acc[16];                              // acc[r*4+kk] = out[wb+r][c2+kk]
#pragma unroll
        for (int j = 0; j < 16; j++) acc[j] = 0.0f;

#pragma unroll 2
        for (int c1i = 0; c1i < 64; c1i += 4) {
            float4 mv0 = *reinterpret_cast<const float4*>(sM + (c1i + 0) * SP + c2);
            float4 mv1 = *reinterpret_cast<const float4*>(sM + (c1i + 1) * SP + c2);
            float4 mv2 = *reinterpret_cast<const float4*>(sM + (c1i + 2) * SP + c2);
            float4 mv3 = *reinterpret_cast<const float4*>(sM + (c1i + 3) * SP + c2);
#pragma unroll
            for (int r = 0; r < 4; r++) {
                float4 qv = *reinterpret_cast<const float4*>(sXP + (wb + r) * SP + c1i);
                acc[r*4+0] += qv.x*mv0.x + qv.y*mv1.x + qv.z*mv2.x + qv.w*mv3.x;
                acc[r*4+1] += qv.x*mv0.y + qv.y*mv1.y + qv.z*mv2.y + qv.w*mv3.y;
                acc[r*4+2] += qv.x*mv0.z + qv.y*mv1.z + qv.z*mv2.z + qv.w*mv3.z;
                acc[r*4+3] += qv.x*mv0.w + qv.y*mv1.w + qv.z*mv2.w + qv.w*mv3.w;
            }
        }

        // residual add + coalesced store (output layout [b][c][h][w])
#pragma unroll
        for (int kk = 0; kk < 4; kk++) {
            int cch = c2 + kk;
            float4 r4 = *reinterpret_cast<const float4*>(sX + cch * SP + wb);
            float4 o4 = make_float4(acc[0*4+kk] + r4.x, acc[1*4+kk] + r4.y,
                                    acc[2*4+kk] + r4.z, acc[3*4+kk] + r4.w);
            *reinterpret_cast<float4*>(ob + (size_t)cch * (HH * WW) + w0 + wb) = o4;
        }
        __syncthreads();
    }
}

extern "C" void kernel_launch(void* const* d_in, const int* in_sizes, int n_in,
                              void* d_out, int out_size)
{
    const float* q  = (const float*)d_in[0];
    const float* k  = (const float*)d_in[1];
    const float* v  = (const float*)d_in[2];
    const float* Wq = (const float*)d_in[3];
    const float* bq = (const float*)d_in[4];
    const float* Wk = (const float*)d_in[5];
    const float* bk = (const float*)d_in[6];
    const float* Wv = (const float*)d_in[7];
    const float* bv = (const float*)d_in[8];
    float* out = (float*)d_out;

    cudaFuncSetAttribute(mha_fused, cudaFuncAttributeMaxDynamicSharedMemorySize, SM_BYTES);

    dim3 grid(HH, BB);
    mha_fused<<<grid, 256, SM_BYTES>>>(q, k, v, Wq, bq, Wk, bk, Wv, bv, out);
}